// round 13
// baseline (speedup 1.0000x reference)
#include <cuda_runtime.h>
#include <math.h>

#define NBATCH 16
#define IH 512
#define IW 512
#define CH2 256
#define CW2 256
#define PLANE_Y (NBATCH * IH * IW)
#define PLANE_C (NBATCH * CH2 * CW2)

#define NT_Y (NBATCH * 64 * 64)   // 65536 luma tiles
#define NT_C (NBATCH * 32 * 32)   // 16384 chroma tiles per plane
#define NT_ALL (NT_Y + 2 * NT_C)  // 98304

#define FWD_LUMA_BLKS (NT_Y / 32)    // 2048 (32 luma tiles/block)
#define FWD_CHROMA_BLKS (NT_C / 16)  // 1024 (16 locations -> 16 U + 16 V tiles/block)
#define XS_STRIDE 68                 // floats; 16B-aligned rows, conflict-free

// ---- scratch planes (static device globals; no runtime allocation) ----
__device__ float g_rY[PLANE_Y];
__device__ float g_rU[PLANE_C];
__device__ float g_rV[PLANE_C];

// ---- compile-time DCT constants, replicating numpy fp64->fp32 exactly ----
__host__ __device__ constexpr double kCosV(int k) {
    return (k == 0) ? 1.0
         : (k == 1) ? 0.98078528040323044913
         : (k == 2) ? 0.92387953251128675613
         : (k == 3) ? 0.83146961230254523708
         : (k == 4) ? 0.70710678118654752440
         : (k == 5) ? 0.55557023301960222474
         : (k == 6) ? 0.38268343236508977173
         : (k == 7) ? 0.19509032201612826785
         : 0.0;
}
__host__ __device__ constexpr double cos16(int k) {
    k &= 31;
    if (k > 16) k = 32 - k;
    return (k <= 8) ? kCosV(k) : -kCosV(16 - k);
}
__host__ __device__ constexpr float Dc(int i, int j) {
    return (float)((j == 0) ? 0.35355339059327376220
                            : 0.5 * cos16((2 * i + 1) * j));
}
struct DTab { float d[8][8]; };
__host__ __device__ constexpr DTab makeD() {
    DTab t{};
    for (int i = 0; i < 8; i++)
        for (int j = 0; j < 8; j++)
            t.d[i][j] = Dc(i, j);
    return t;
}
__device__ constexpr DTab DM = makeD();

// ---- exact reference CSC pieces (validated bit-exact) ----
__device__ __forceinline__ float csc_y(float rr, float gg, float bb) {
    float r  = __fmul_rn(rr, 255.0f);
    float g  = __fmul_rn(gg, 255.0f);
    float bl = __fmul_rn(bb, 255.0f);
    return __fadd_rn(__fadd_rn(__fmul_rn(r, 0.299f), __fmul_rn(g, 0.587f)),
                     __fmul_rn(bl, 0.114f));
}
__device__ __forceinline__ float csc_u(float rr, float gg, float bb) {
    float r  = __fmul_rn(rr, 255.0f);
    float g  = __fmul_rn(gg, 255.0f);
    float bl = __fmul_rn(bb, 255.0f);
    return __fadd_rn(__fadd_rn(__fadd_rn(__fmul_rn(r, -0.168736f),
                                         __fmul_rn(g, -0.331264f)),
                               __fmul_rn(bl, 0.5f)), 128.0f);
}
__device__ __forceinline__ float csc_v(float rr, float gg, float bb) {
    float r  = __fmul_rn(rr, 255.0f);
    float g  = __fmul_rn(gg, 255.0f);
    float bl = __fmul_rn(bb, 255.0f);
    return __fadd_rn(__fadd_rn(__fadd_rn(__fmul_rn(r, 0.5f),
                                         __fmul_rn(g, -0.418688f)),
                               __fmul_rn(bl, -0.081312f)), 128.0f);
}

// ---- separable forward row transform (fast path; order is free) ----
__device__ __forceinline__ void fwd_row(const float xr[8], float tr[8])
{
#pragma unroll
    for (int j = 0; j < 8; j++) {
        float s = 0.f;
#pragma unroll
        for (int k = 0; k < 8; k++)
            s = fmaf(xr[k], Dc(k, j), s);
        tr[j] = s;
    }
}

// ---- column pass + quantize with exact-rounding guard ----
// Fast: separable ratio. If within 0.02 of a half-integer boundary,
// recompute the single coefficient with the VALIDATED exact kron-sequential
// order (pp = 0..63, w = fl32mul(D[pr][I], D[pc][j])) -> q bit-exact.
template<int I>
__device__ __forceinline__ void fwd_col(const float* __restrict__ tt,
                                        const float* __restrict__ xx,
                                        const float* __restrict__ qt,
                                        float* __restrict__ qo)
{
    float C[8] = {0.f, 0.f, 0.f, 0.f, 0.f, 0.f, 0.f, 0.f};
#pragma unroll
    for (int r = 0; r < 8; r++) {
        float4 a = *(const float4*)(tt + r * 8);
        float4 b = *(const float4*)(tt + r * 8 + 4);
        float Tv[8] = {a.x, a.y, a.z, a.w, b.x, b.y, b.z, b.w};
#pragma unroll
        for (int j = 0; j < 8; j++)
            C[j] = fmaf(Dc(r, I), Tv[j], C[j]);
    }
    float q[8];
#pragma unroll
    for (int j = 0; j < 8; j++) {
        float qtv = qt[I * 8 + j];
        float ratio = __fdiv_rn(C[j], qtv);
        float fr = fabsf(ratio - rintf(ratio));
        if (fr > 0.48f) {
            // slow path: exact kron-sequential accumulation (validated order)
            float a = 0.f;
#pragma unroll 4
            for (int pp = 0; pp < 64; pp++)
                a = fmaf(xx[pp], __fmul_rn(DM.d[pp >> 3][I], DM.d[pp & 7][j]), a);
            ratio = __fdiv_rn(a, qtv);
        }
        q[j] = rintf(ratio);
    }
    *(float4*)(qo + I * 8)     = make_float4(q[0], q[1], q[2], q[3]);
    *(float4*)(qo + I * 8 + 4) = make_float4(q[4], q[5], q[6], q[7]);
}

// ---- fused CSC + separable forward DCT + guarded quantize ----
// 256 threads = 32 tiles (8 threads/tile). Luma blocks: 32 Y tiles.
// Chroma blocks: 16 locations -> 16 U + 16 V tiles (one RGB read for both).
__global__ void __launch_bounds__(256) k_fwd(const float* __restrict__ img,
                                             const float* __restrict__ lq,
                                             const float* __restrict__ cq,
                                             float* __restrict__ qY,
                                             float* __restrict__ qU,
                                             float* __restrict__ qV)
{
    __shared__ float xs[32 * XS_STRIDE];   // raw x (pixel-128) per tile
    __shared__ float ts[32 * XS_STRIDE];   // row-transformed per tile
    __shared__ float Qs[2][64];

    int t = threadIdx.x;
    if (t < 64)       Qs[0][t]      = lq[t];
    else if (t < 128) Qs[1][t - 64] = cq[t - 64];

    int tileL = t & 31;
    int row   = t >> 5;

    if (blockIdx.x < FWD_LUMA_BLKS) {
        // thread (tileL,row): one 8-px row of Y via exact CSC -> xs
        int tp = blockIdx.x * 32 + tileL;
        int b  = tp >> 12;
        int r2 = tp & 4095;
        int by = r2 >> 6, bx = r2 & 63;
        const float* Rp = img + (size_t)b * 3 * IH * IW
                              + (size_t)(by * 8 + row) * IW + bx * 8;
        const float* Gp = Rp + IH * IW;
        const float* Bp = Rp + 2 * IH * IW;
        float4 r0 = *(const float4*)(Rp), r1 = *(const float4*)(Rp + 4);
        float4 g0 = *(const float4*)(Gp), g1 = *(const float4*)(Gp + 4);
        float4 b0 = *(const float4*)(Bp), b1 = *(const float4*)(Bp + 4);
        float* xr = xs + tileL * XS_STRIDE + row * 8;
        *(float4*)(xr) = make_float4(csc_y(r0.x, g0.x, b0.x) - 128.f,
                                     csc_y(r0.y, g0.y, b0.y) - 128.f,
                                     csc_y(r0.z, g0.z, b0.z) - 128.f,
                                     csc_y(r0.w, g0.w, b0.w) - 128.f);
        *(float4*)(xr + 4) = make_float4(csc_y(r1.x, g1.x, b1.x) - 128.f,
                                         csc_y(r1.y, g1.y, b1.y) - 128.f,
                                         csc_y(r1.z, g1.z, b1.z) - 128.f,
                                         csc_y(r1.w, g1.w, b1.w) - 128.f);
    } else {
        // chroma: 1024 sites (16 locations x 64), 4 per thread; one RGB read
        // fills BOTH the U row (tiles 0..15) and V row (tiles 16..31) of xs.
        int cblk = blockIdx.x - FWD_LUMA_BLKS;
        int loc0 = cblk * 16;
#pragma unroll
        for (int k = 0; k < 4; k++) {
            int sidx = t + k * 256;
            int s = sidx >> 6;
            int q = sidx & 63;
            int qy = q >> 3, qx = q & 7;
            int loc = loc0 + s;
            int b  = loc >> 10;
            int r2 = loc & 1023;
            int ty = r2 >> 5, tx = r2 & 31;
            int cy = ty * 8 + qy, cx = tx * 8 + qx;
            const float* Rp = img + (size_t)b * 3 * IH * IW;
            const float* Gp = Rp + IH * IW;
            const float* Bp = Rp + 2 * IH * IW;
            int o0 = (cy * 2) * IW + cx * 2;
            int o1 = o0 + IW;
            float2 r0 = *(const float2*)(Rp + o0), r1 = *(const float2*)(Rp + o1);
            float2 g0 = *(const float2*)(Gp + o0), g1 = *(const float2*)(Gp + o1);
            float2 b0 = *(const float2*)(Bp + o0), b1 = *(const float2*)(Bp + o1);
            float u0 = csc_u(r0.x, g0.x, b0.x), u1 = csc_u(r0.y, g0.y, b0.y);
            float u2 = csc_u(r1.x, g1.x, b1.x), u3 = csc_u(r1.y, g1.y, b1.y);
            float v0 = csc_v(r0.x, g0.x, b0.x), v1 = csc_v(r0.y, g0.y, b0.y);
            float v2 = csc_v(r1.x, g1.x, b1.x), v3 = csc_v(r1.y, g1.y, b1.y);
            float um = __fmul_rn(__fadd_rn(__fadd_rn(u0, u1), __fadd_rn(u2, u3)), 0.25f);
            float vm = __fmul_rn(__fadd_rn(__fadd_rn(v0, v1), __fadd_rn(v2, v3)), 0.25f);
            xs[s * XS_STRIDE + q]        = um - 128.f;
            xs[(16 + s) * XS_STRIDE + q] = vm - 128.f;
        }
    }
    __syncthreads();

    // row transform: thread (tileL,row) -> ts
    {
        const float* xr4 = xs + tileL * XS_STRIDE + row * 8;
        float4 a = *(const float4*)(xr4);
        float4 b = *(const float4*)(xr4 + 4);
        float xr[8] = {a.x, a.y, a.z, a.w, b.x, b.y, b.z, b.w};
        float tr[8];
        fwd_row(xr, tr);
        float* td = ts + tileL * XS_STRIDE + row * 8;
        *(float4*)(td)     = make_float4(tr[0], tr[1], tr[2], tr[3]);
        *(float4*)(td + 4) = make_float4(tr[4], tr[5], tr[6], tr[7]);
    }
    __syncthreads();

    // column pass + guarded quantize
    const float* qt;
    float* qo;
    if (blockIdx.x < FWD_LUMA_BLKS) {
        qt = Qs[0];
        qo = qY + (size_t)(blockIdx.x * 32 + tileL) * 64;
    } else {
        qt = Qs[1];
        int cblk = blockIdx.x - FWD_LUMA_BLKS;
        int loc = cblk * 16 + (tileL & 15);
        qo = ((tileL >= 16) ? qV : qU) + (size_t)loc * 64;
    }
    const float* tt = ts + tileL * XS_STRIDE;
    const float* xx = xs + tileL * XS_STRIDE;
    switch (row) {
        case 0: fwd_col<0>(tt, xx, qt, qo); break;
        case 1: fwd_col<1>(tt, xx, qt, qo); break;
        case 2: fwd_col<2>(tt, xx, qt, qo); break;
        case 3: fwd_col<3>(tt, xx, qt, qo); break;
        case 4: fwd_col<4>(tt, xx, qt, qo); break;
        case 5: fwd_col<5>(tt, xx, qt, qo); break;
        case 6: fwd_col<6>(tt, xx, qt, qo); break;
        case 7: fwd_col<7>(tt, xx, qt, qo); break;
    }
}

// ---- inverse rows for output row R (immediate D consts) ----
template<int R>
__device__ __forceinline__ void inv_rows(const float* __restrict__ cl, float o[8])
{
    float T[8] = {0.f, 0.f, 0.f, 0.f, 0.f, 0.f, 0.f, 0.f};
#pragma unroll
    for (int j1 = 0; j1 < 8; j1++) {
        float4 ca = *(const float4*)(cl + j1 * 8);
        float4 cb = *(const float4*)(cl + j1 * 8 + 4);
        float cv[8] = {ca.x, ca.y, ca.z, ca.w, cb.x, cb.y, cb.z, cb.w};
#pragma unroll
        for (int j2 = 0; j2 < 8; j2++)
            T[j2] = fmaf(Dc(R, j1), cv[j2], T[j2]);
    }
#pragma unroll
    for (int c = 0; c < 8; c++) {
        float s = 0.f;
#pragma unroll
        for (int j2 = 0; j2 < 8; j2++)
            s = fmaf(T[j2], Dc(c, j2), s);
        o[c] = s + 128.f;
    }
}

// ---- fused inverse: all planes, 8 threads/tile ----
__global__ void __launch_bounds__(256) k_inv(const float* __restrict__ lq,
                                             const float* __restrict__ cq,
                                             const float* __restrict__ qY,
                                             const float* __restrict__ qU,
                                             const float* __restrict__ qV)
{
    __shared__ float Cs[32 * XS_STRIDE];
    __shared__ float Qs[2][64];

    int t = threadIdx.x;
    if (t < 64)       Qs[0][t]      = lq[t];
    else if (t < 128) Qs[1][t - 64] = cq[t - 64];
    __syncthreads();

    int tileL = t & 31;
    int row   = t >> 5;
    int tile  = blockIdx.x * 32 + tileL;

    const float* qbase; float* rec; int width, qsel; int tp;
    if (tile < NT_Y)            { tp = tile;               qbase = qY; rec = g_rY; width = IW;  qsel = 0; }
    else if (tile < NT_Y+NT_C)  { tp = tile - NT_Y;        qbase = qU; rec = g_rU; width = CW2; qsel = 1; }
    else                        { tp = tile - NT_Y - NT_C; qbase = qV; rec = g_rV; width = CW2; qsel = 1; }
    int nbx  = width >> 3;
    int nbpi = nbx * nbx;
    int b  = tp / nbpi, r = tp - b * nbpi;
    int by = r / nbx,  bx = r - by * nbx;
    size_t po = ((size_t)b * width + by * 8) * width + bx * 8;

    {
        const float* qi = qbase + (size_t)tp * 64 + row * 8;
        float4 v0 = *(const float4*)(qi);
        float4 v1 = *(const float4*)(qi + 4);
        const float* Qt = Qs[qsel] + row * 8;
        float* cr = Cs + tileL * XS_STRIDE + row * 8;
        *(float4*)(cr)     = make_float4(__fmul_rn(v0.x, Qt[0]), __fmul_rn(v0.y, Qt[1]),
                                         __fmul_rn(v0.z, Qt[2]), __fmul_rn(v0.w, Qt[3]));
        *(float4*)(cr + 4) = make_float4(__fmul_rn(v1.x, Qt[4]), __fmul_rn(v1.y, Qt[5]),
                                         __fmul_rn(v1.z, Qt[6]), __fmul_rn(v1.w, Qt[7]));
    }
    __syncthreads();

    float o[8];
    const float* cl = Cs + tileL * XS_STRIDE;
    switch (row) {
        case 0: inv_rows<0>(cl, o); break;
        case 1: inv_rows<1>(cl, o); break;
        case 2: inv_rows<2>(cl, o); break;
        case 3: inv_rows<3>(cl, o); break;
        case 4: inv_rows<4>(cl, o); break;
        case 5: inv_rows<5>(cl, o); break;
        case 6: inv_rows<6>(cl, o); break;
        case 7: inv_rows<7>(cl, o); break;
    }

    float* rp = rec + po + (size_t)row * width;
    *(float4*)(rp)     = make_float4(o[0], o[1], o[2], o[3]);
    *(float4*)(rp + 4) = make_float4(o[4], o[5], o[6], o[7]);
}

// ---- strip recon: one thread per 4 quads (8x2 pixels); bit-exact lerps ----
__global__ void __launch_bounds__(256) k_recon(float* __restrict__ out)
{
    int t = blockIdx.x * blockDim.x + threadIdx.x;
    if (t >= PLANE_C / 4) return;
    int sx = t & 63;
    int cy = (t >> 6) & 255;
    int b  = t >> 14;
    int cx0 = sx << 2;

    size_t cb = (size_t)b * CH2 * CW2;
    const float* Up = g_rU + cb;
    const float* Vp = g_rV + cb;

    int cym = max(cy - 1, 0), cyp = min(cy + 1, 255);
    bool y_top = (cy == 0), y_bot = (cy == 255);
    int colL = max(cx0 - 1, 0);
    int colR = min(cx0 + 4, 255);

    float uA[6], uM[6], uP[6], vA[6], vM[6], vP[6];
#define LOADROW(dst, base) { \
        float4 m = *(const float4*)((base) + cx0); \
        dst[1] = m.x; dst[2] = m.y; dst[3] = m.z; dst[4] = m.w; \
        dst[0] = (base)[colL]; dst[5] = (base)[colR]; }
    LOADROW(uA, Up + cym * CW2)
    LOADROW(uM, Up + cy  * CW2)
    LOADROW(uP, Up + cyp * CW2)
    LOADROW(vA, Vp + cym * CW2)
    LOADROW(vM, Vp + cy  * CW2)
    LOADROW(vP, Vp + cyp * CW2)
#undef LOADROW

    float ue[6], uo[6], ve[6], vo[6];
#pragma unroll
    for (int c = 0; c < 6; c++) {
        ue[c] = y_top ? uM[c] : __fadd_rn(__fmul_rn(uA[c], 0.25f), __fmul_rn(uM[c], 0.75f));
        uo[c] = y_bot ? uM[c] : __fadd_rn(__fmul_rn(uM[c], 0.75f), __fmul_rn(uP[c], 0.25f));
        ve[c] = y_top ? vM[c] : __fadd_rn(__fmul_rn(vA[c], 0.25f), __fmul_rn(vM[c], 0.75f));
        vo[c] = y_bot ? vM[c] : __fadd_rn(__fmul_rn(vM[c], 0.75f), __fmul_rn(vP[c], 0.25f));
    }

    float u00[4], u01[4], u10[4], u11[4];
    float v00[4], v01[4], v10[4], v11[4];
#pragma unroll
    for (int j = 0; j < 4; j++) {
        int ci = j + 1;
        bool xl = (cx0 + j == 0);
        bool xr = (cx0 + j == 255);
        u00[j] = xl ? ue[ci] : __fadd_rn(__fmul_rn(ue[ci-1], 0.25f), __fmul_rn(ue[ci], 0.75f));
        u01[j] = xr ? ue[ci] : __fadd_rn(__fmul_rn(ue[ci], 0.75f), __fmul_rn(ue[ci+1], 0.25f));
        u10[j] = xl ? uo[ci] : __fadd_rn(__fmul_rn(uo[ci-1], 0.25f), __fmul_rn(uo[ci], 0.75f));
        u11[j] = xr ? uo[ci] : __fadd_rn(__fmul_rn(uo[ci], 0.75f), __fmul_rn(uo[ci+1], 0.25f));
        v00[j] = xl ? ve[ci] : __fadd_rn(__fmul_rn(ve[ci-1], 0.25f), __fmul_rn(ve[ci], 0.75f));
        v01[j] = xr ? ve[ci] : __fadd_rn(__fmul_rn(ve[ci], 0.75f), __fmul_rn(ve[ci+1], 0.25f));
        v10[j] = xl ? vo[ci] : __fadd_rn(__fmul_rn(vo[ci-1], 0.25f), __fmul_rn(vo[ci], 0.75f));
        v11[j] = xr ? vo[ci] : __fadd_rn(__fmul_rn(vo[ci], 0.75f), __fmul_rn(vo[ci+1], 0.25f));
    }

    size_t yo0 = ((size_t)b * IH + cy * 2) * IW + cx0 * 2;
    float4 ya0 = *(const float4*)(g_rY + yo0);
    float4 ya1 = *(const float4*)(g_rY + yo0 + 4);
    float4 yb0 = *(const float4*)(g_rY + yo0 + IW);
    float4 yb1 = *(const float4*)(g_rY + yo0 + IW + 4);
    float ytop[8] = {ya0.x, ya0.y, ya0.z, ya0.w, ya1.x, ya1.y, ya1.z, ya1.w};
    float ybot[8] = {yb0.x, yb0.y, yb0.z, yb0.w, yb1.x, yb1.y, yb1.z, yb1.w};

    float R0[8], G0[8], B0[8], R1[8], G1[8], B1[8];
#pragma unroll
    for (int k = 0; k < 8; k++) {
        int j = k >> 1;
        bool odd = k & 1;
        {
            float uu = __fadd_rn(odd ? u01[j] : u00[j], -128.0f);
            float vv = __fadd_rn(odd ? v01[j] : v00[j], -128.0f);
            float yv = ytop[k];
            float r  = __fadd_rn(yv, __fmul_rn(vv, 1.402f));
            float g  = __fadd_rn(__fadd_rn(yv, __fmul_rn(uu, -0.344136f)), __fmul_rn(vv, -0.714136f));
            float bl = __fadd_rn(yv, __fmul_rn(uu, 1.772f));
            R0[k] = __fdiv_rn(fminf(fmaxf(r,  0.f), 255.f), 255.0f);
            G0[k] = __fdiv_rn(fminf(fmaxf(g,  0.f), 255.f), 255.0f);
            B0[k] = __fdiv_rn(fminf(fmaxf(bl, 0.f), 255.f), 255.0f);
        }
        {
            float uu = __fadd_rn(odd ? u11[j] : u10[j], -128.0f);
            float vv = __fadd_rn(odd ? v11[j] : v10[j], -128.0f);
            float yv = ybot[k];
            float r  = __fadd_rn(yv, __fmul_rn(vv, 1.402f));
            float g  = __fadd_rn(__fadd_rn(yv, __fmul_rn(uu, -0.344136f)), __fmul_rn(vv, -0.714136f));
            float bl = __fadd_rn(yv, __fmul_rn(uu, 1.772f));
            R1[k] = __fdiv_rn(fminf(fmaxf(r,  0.f), 255.f), 255.0f);
            G1[k] = __fdiv_rn(fminf(fmaxf(g,  0.f), 255.f), 255.0f);
            B1[k] = __fdiv_rn(fminf(fmaxf(bl, 0.f), 255.f), 255.0f);
        }
    }

    size_t ob0 = (size_t)b * 3 * IH * IW + ((size_t)cy * 2) * IW + cx0 * 2;
    size_t ob1 = ob0 + IW;
#define STORE8(base, arr) { \
        *(float4*)(base)     = make_float4(arr[0], arr[1], arr[2], arr[3]); \
        *(float4*)((base)+4) = make_float4(arr[4], arr[5], arr[6], arr[7]); }
    STORE8(out + ob0, R0)
    STORE8(out + ob1, R1)
    STORE8(out + ob0 + IH * IW, G0)
    STORE8(out + ob1 + IH * IW, G1)
    STORE8(out + ob0 + 2 * IH * IW, B0)
    STORE8(out + ob1 + 2 * IH * IW, B1)
#undef STORE8
}

extern "C" void kernel_launch(void* const* d_in, const int* in_sizes, int n_in,
                              void* d_out, int out_size)
{
    const float* img = (const float*)d_in[0];
    const float* lq  = (const float*)d_in[1];
    const float* cq  = (const float*)d_in[2];
    float* out = (float*)d_out;

    // output layout: rgb | qY | qU | qV (reference return order, flattened)
    float* qY = out + 12582912;
    float* qU = out + 16777216;
    float* qV = out + 17825792;

    k_fwd<<<FWD_LUMA_BLKS + FWD_CHROMA_BLKS, 256>>>(img, lq, cq, qY, qU, qV);
    k_inv<<<NT_ALL / 32, 256>>>(lq, cq, qY, qU, qV);
    k_recon<<<(PLANE_C / 4 + 255) / 256, 256>>>(out);
}

// round 14
// speedup vs baseline: 2.2665x; 2.2665x over previous
#include <cuda_runtime.h>
#include <math.h>

#define NBATCH 16
#define IH 512
#define IW 512
#define CH2 256
#define CW2 256
#define PLANE_Y (NBATCH * IH * IW)
#define PLANE_C (NBATCH * CH2 * CW2)

#define NT_Y (NBATCH * 64 * 64)   // 65536 luma tiles
#define NT_C (NBATCH * 32 * 32)   // 16384 chroma tiles per plane
#define NT_ALL (NT_Y + 2 * NT_C)  // 98304

#define FWD_LUMA_BLKS (NT_Y / 32)    // 2048 (32 luma tiles/block)
#define FWD_CHROMA_BLKS (NT_C / 16)  // 1024 (16 locations -> 16 U + 16 V tiles/block)
#define XS_STRIDE 68                 // floats; 16B-aligned rows, conflict-free

// ---- scratch planes (static device globals; no runtime allocation) ----
__device__ float g_rY[PLANE_Y];
__device__ float g_rU[PLANE_C];
__device__ float g_rV[PLANE_C];

// ---- compile-time DCT constants, replicating numpy fp64->fp32 exactly ----
__host__ __device__ constexpr double kCosV(int k) {
    return (k == 0) ? 1.0
         : (k == 1) ? 0.98078528040323044913
         : (k == 2) ? 0.92387953251128675613
         : (k == 3) ? 0.83146961230254523708
         : (k == 4) ? 0.70710678118654752440
         : (k == 5) ? 0.55557023301960222474
         : (k == 6) ? 0.38268343236508977173
         : (k == 7) ? 0.19509032201612826785
         : 0.0;
}
__host__ __device__ constexpr double cos16(int k) {
    k &= 31;
    if (k > 16) k = 32 - k;
    return (k <= 8) ? kCosV(k) : -kCosV(16 - k);
}
__host__ __device__ constexpr float Dc(int i, int j) {
    return (float)((j == 0) ? 0.35355339059327376220
                            : 0.5 * cos16((2 * i + 1) * j));
}
struct DTab { float d[8][8]; };
__host__ __device__ constexpr DTab makeD() {
    DTab t{};
    for (int i = 0; i < 8; i++)
        for (int j = 0; j < 8; j++)
            t.d[i][j] = Dc(i, j);
    return t;
}
__device__ constexpr DTab DM = makeD();

// ---- exact reference CSC pieces (validated bit-exact) ----
__device__ __forceinline__ float csc_y(float rr, float gg, float bb) {
    float r  = __fmul_rn(rr, 255.0f);
    float g  = __fmul_rn(gg, 255.0f);
    float bl = __fmul_rn(bb, 255.0f);
    return __fadd_rn(__fadd_rn(__fmul_rn(r, 0.299f), __fmul_rn(g, 0.587f)),
                     __fmul_rn(bl, 0.114f));
}
__device__ __forceinline__ float csc_u(float rr, float gg, float bb) {
    float r  = __fmul_rn(rr, 255.0f);
    float g  = __fmul_rn(gg, 255.0f);
    float bl = __fmul_rn(bb, 255.0f);
    return __fadd_rn(__fadd_rn(__fadd_rn(__fmul_rn(r, -0.168736f),
                                         __fmul_rn(g, -0.331264f)),
                               __fmul_rn(bl, 0.5f)), 128.0f);
}
__device__ __forceinline__ float csc_v(float rr, float gg, float bb) {
    float r  = __fmul_rn(rr, 255.0f);
    float g  = __fmul_rn(gg, 255.0f);
    float bl = __fmul_rn(bb, 255.0f);
    return __fadd_rn(__fadd_rn(__fadd_rn(__fmul_rn(r, 0.5f),
                                         __fmul_rn(g, -0.418688f)),
                               __fmul_rn(bl, -0.081312f)), 128.0f);
}

// ---- separable forward row transform (fast path; order is free) ----
__device__ __forceinline__ void fwd_row(const float xr[8], float tr[8])
{
#pragma unroll
    for (int j = 0; j < 8; j++) {
        float s = 0.f;
#pragma unroll
        for (int k = 0; k < 8; k++)
            s = fmaf(xr[k], Dc(k, j), s);
        tr[j] = s;
    }
}

// ---- column pass + quantize with exact-rounding guard ----
// Fast: separable ratio; suspects (within 0.02 of a half-integer boundary)
// are collected in a bitmask and drained AFTER the unrolled loop, each with
// the VALIDATED exact kron-sequential order:
//   a = fold_{pp=0..63} fma(x[pp], fl32(D[pp>>3][I] * D[pp&7][j]), a)
// D[pr][I] are template immediates; D[pc][j] come from an 8-register block
// loaded from the smem D-table. q output is bit-identical (guard validated R13).
template<int I>
__device__ __forceinline__ void fwd_col(const float* __restrict__ tt,
                                        const float* __restrict__ xx,
                                        const float* __restrict__ qt,
                                        const float* __restrict__ Ds,
                                        float* __restrict__ qo)
{
    float C[8] = {0.f, 0.f, 0.f, 0.f, 0.f, 0.f, 0.f, 0.f};
#pragma unroll
    for (int r = 0; r < 8; r++) {
        float4 a = *(const float4*)(tt + r * 8);
        float4 b = *(const float4*)(tt + r * 8 + 4);
        float Tv[8] = {a.x, a.y, a.z, a.w, b.x, b.y, b.z, b.w};
#pragma unroll
        for (int j = 0; j < 8; j++)
            C[j] = fmaf(Dc(r, I), Tv[j], C[j]);
    }
    float q[8];
    unsigned mask = 0;
#pragma unroll
    for (int j = 0; j < 8; j++) {
        float ratio = __fdiv_rn(C[j], qt[I * 8 + j]);
        float fr = fabsf(ratio - rintf(ratio));
        if (fr > 0.48f) mask |= 1u << j;
        q[j] = rintf(ratio);
    }
    // rare exact path: drain suspect mask (max-over-lanes iterations)
    while (mask) {
        int j = __ffs(mask) - 1;
        mask &= mask - 1;
        float Dj[8];
#pragma unroll
        for (int pc = 0; pc < 8; pc++) Dj[pc] = Ds[pc * 8 + j];
        float a = 0.f;
#pragma unroll
        for (int pp = 0; pp < 64; pp++)
            a = fmaf(xx[pp], __fmul_rn(Dc(pp >> 3, I), Dj[pp & 7]), a);
        q[j] = rintf(__fdiv_rn(a, qt[I * 8 + j]));
    }
    *(float4*)(qo + I * 8)     = make_float4(q[0], q[1], q[2], q[3]);
    *(float4*)(qo + I * 8 + 4) = make_float4(q[4], q[5], q[6], q[7]);
}

// ---- fused CSC + separable forward DCT + guarded quantize ----
// 256 threads = 32 tiles (8 threads/tile). Luma blocks: 32 Y tiles.
// Chroma blocks: 16 locations -> 16 U + 16 V tiles (one RGB read for both).
__global__ void __launch_bounds__(256) k_fwd(const float* __restrict__ img,
                                             const float* __restrict__ lq,
                                             const float* __restrict__ cq,
                                             float* __restrict__ qY,
                                             float* __restrict__ qU,
                                             float* __restrict__ qV)
{
    __shared__ float xs[32 * XS_STRIDE];   // raw x (pixel-128) per tile
    __shared__ float ts[32 * XS_STRIDE];   // row-transformed per tile
    __shared__ float Qs[2][64];
    __shared__ float Ds[64];               // D[i][j] at i*8+j (slow-path table)

    int t = threadIdx.x;
    if (t < 64)        Qs[0][t]       = lq[t];
    else if (t < 128)  Qs[1][t - 64]  = cq[t - 64];
    else if (t < 192)  Ds[t - 128]    = DM.d[(t - 128) >> 3][(t - 128) & 7];

    int tileL = t & 31;
    int row   = t >> 5;

    if (blockIdx.x < FWD_LUMA_BLKS) {
        // thread (tileL,row): one 8-px row of Y via exact CSC -> xs
        int tp = blockIdx.x * 32 + tileL;
        int b  = tp >> 12;
        int r2 = tp & 4095;
        int by = r2 >> 6, bx = r2 & 63;
        const float* Rp = img + (size_t)b * 3 * IH * IW
                              + (size_t)(by * 8 + row) * IW + bx * 8;
        const float* Gp = Rp + IH * IW;
        const float* Bp = Rp + 2 * IH * IW;
        float4 r0 = *(const float4*)(Rp), r1 = *(const float4*)(Rp + 4);
        float4 g0 = *(const float4*)(Gp), g1 = *(const float4*)(Gp + 4);
        float4 b0 = *(const float4*)(Bp), b1 = *(const float4*)(Bp + 4);
        float* xr = xs + tileL * XS_STRIDE + row * 8;
        *(float4*)(xr) = make_float4(csc_y(r0.x, g0.x, b0.x) - 128.f,
                                     csc_y(r0.y, g0.y, b0.y) - 128.f,
                                     csc_y(r0.z, g0.z, b0.z) - 128.f,
                                     csc_y(r0.w, g0.w, b0.w) - 128.f);
        *(float4*)(xr + 4) = make_float4(csc_y(r1.x, g1.x, b1.x) - 128.f,
                                         csc_y(r1.y, g1.y, b1.y) - 128.f,
                                         csc_y(r1.z, g1.z, b1.z) - 128.f,
                                         csc_y(r1.w, g1.w, b1.w) - 128.f);
    } else {
        // chroma: 1024 sites (16 locations x 64), 4 per thread; one RGB read
        // fills BOTH the U row (tiles 0..15) and V row (tiles 16..31) of xs.
        int cblk = blockIdx.x - FWD_LUMA_BLKS;
        int loc0 = cblk * 16;
#pragma unroll
        for (int k = 0; k < 4; k++) {
            int sidx = t + k * 256;
            int s = sidx >> 6;
            int q = sidx & 63;
            int qy = q >> 3, qx = q & 7;
            int loc = loc0 + s;
            int b  = loc >> 10;
            int r2 = loc & 1023;
            int ty = r2 >> 5, tx = r2 & 31;
            int cy = ty * 8 + qy, cx = tx * 8 + qx;
            const float* Rp = img + (size_t)b * 3 * IH * IW;
            const float* Gp = Rp + IH * IW;
            const float* Bp = Rp + 2 * IH * IW;
            int o0 = (cy * 2) * IW + cx * 2;
            int o1 = o0 + IW;
            float2 r0 = *(const float2*)(Rp + o0), r1 = *(const float2*)(Rp + o1);
            float2 g0 = *(const float2*)(Gp + o0), g1 = *(const float2*)(Gp + o1);
            float2 b0 = *(const float2*)(Bp + o0), b1 = *(const float2*)(Bp + o1);
            float u0 = csc_u(r0.x, g0.x, b0.x), u1 = csc_u(r0.y, g0.y, b0.y);
            float u2 = csc_u(r1.x, g1.x, b1.x), u3 = csc_u(r1.y, g1.y, b1.y);
            float v0 = csc_v(r0.x, g0.x, b0.x), v1 = csc_v(r0.y, g0.y, b0.y);
            float v2 = csc_v(r1.x, g1.x, b1.x), v3 = csc_v(r1.y, g1.y, b1.y);
            float um = __fmul_rn(__fadd_rn(__fadd_rn(u0, u1), __fadd_rn(u2, u3)), 0.25f);
            float vm = __fmul_rn(__fadd_rn(__fadd_rn(v0, v1), __fadd_rn(v2, v3)), 0.25f);
            xs[s * XS_STRIDE + q]        = um - 128.f;
            xs[(16 + s) * XS_STRIDE + q] = vm - 128.f;
        }
    }
    __syncthreads();

    // row transform: thread (tileL,row) -> ts
    {
        const float* xr4 = xs + tileL * XS_STRIDE + row * 8;
        float4 a = *(const float4*)(xr4);
        float4 b = *(const float4*)(xr4 + 4);
        float xr[8] = {a.x, a.y, a.z, a.w, b.x, b.y, b.z, b.w};
        float tr[8];
        fwd_row(xr, tr);
        float* td = ts + tileL * XS_STRIDE + row * 8;
        *(float4*)(td)     = make_float4(tr[0], tr[1], tr[2], tr[3]);
        *(float4*)(td + 4) = make_float4(tr[4], tr[5], tr[6], tr[7]);
    }
    __syncthreads();

    // column pass + guarded quantize
    const float* qt;
    float* qo;
    if (blockIdx.x < FWD_LUMA_BLKS) {
        qt = Qs[0];
        qo = qY + (size_t)(blockIdx.x * 32 + tileL) * 64;
    } else {
        qt = Qs[1];
        int cblk = blockIdx.x - FWD_LUMA_BLKS;
        int loc = cblk * 16 + (tileL & 15);
        qo = ((tileL >= 16) ? qV : qU) + (size_t)loc * 64;
    }
    const float* tt = ts + tileL * XS_STRIDE;
    const float* xx = xs + tileL * XS_STRIDE;
    switch (row) {
        case 0: fwd_col<0>(tt, xx, qt, Ds, qo); break;
        case 1: fwd_col<1>(tt, xx, qt, Ds, qo); break;
        case 2: fwd_col<2>(tt, xx, qt, Ds, qo); break;
        case 3: fwd_col<3>(tt, xx, qt, Ds, qo); break;
        case 4: fwd_col<4>(tt, xx, qt, Ds, qo); break;
        case 5: fwd_col<5>(tt, xx, qt, Ds, qo); break;
        case 6: fwd_col<6>(tt, xx, qt, Ds, qo); break;
        case 7: fwd_col<7>(tt, xx, qt, Ds, qo); break;
    }
}

// ---- inverse rows for output row R (immediate D consts) ----
template<int R>
__device__ __forceinline__ void inv_rows(const float* __restrict__ cl, float o[8])
{
    float T[8] = {0.f, 0.f, 0.f, 0.f, 0.f, 0.f, 0.f, 0.f};
#pragma unroll
    for (int j1 = 0; j1 < 8; j1++) {
        float4 ca = *(const float4*)(cl + j1 * 8);
        float4 cb = *(const float4*)(cl + j1 * 8 + 4);
        float cv[8] = {ca.x, ca.y, ca.z, ca.w, cb.x, cb.y, cb.z, cb.w};
#pragma unroll
        for (int j2 = 0; j2 < 8; j2++)
            T[j2] = fmaf(Dc(R, j1), cv[j2], T[j2]);
    }
#pragma unroll
    for (int c = 0; c < 8; c++) {
        float s = 0.f;
#pragma unroll
        for (int j2 = 0; j2 < 8; j2++)
            s = fmaf(T[j2], Dc(c, j2), s);
        o[c] = s + 128.f;
    }
}

// ---- fused inverse: all planes, 8 threads/tile ----
__global__ void __launch_bounds__(256) k_inv(const float* __restrict__ lq,
                                             const float* __restrict__ cq,
                                             const float* __restrict__ qY,
                                             const float* __restrict__ qU,
                                             const float* __restrict__ qV)
{
    __shared__ float Cs[32 * XS_STRIDE];
    __shared__ float Qs[2][64];

    int t = threadIdx.x;
    if (t < 64)       Qs[0][t]      = lq[t];
    else if (t < 128) Qs[1][t - 64] = cq[t - 64];
    __syncthreads();

    int tileL = t & 31;
    int row   = t >> 5;
    int tile  = blockIdx.x * 32 + tileL;

    const float* qbase; float* rec; int width, qsel; int tp;
    if (tile < NT_Y)            { tp = tile;               qbase = qY; rec = g_rY; width = IW;  qsel = 0; }
    else if (tile < NT_Y+NT_C)  { tp = tile - NT_Y;        qbase = qU; rec = g_rU; width = CW2; qsel = 1; }
    else                        { tp = tile - NT_Y - NT_C; qbase = qV; rec = g_rV; width = CW2; qsel = 1; }
    int nbx  = width >> 3;
    int nbpi = nbx * nbx;
    int b  = tp / nbpi, r = tp - b * nbpi;
    int by = r / nbx,  bx = r - by * nbx;
    size_t po = ((size_t)b * width + by * 8) * width + bx * 8;

    {
        const float* qi = qbase + (size_t)tp * 64 + row * 8;
        float4 v0 = *(const float4*)(qi);
        float4 v1 = *(const float4*)(qi + 4);
        const float* Qt = Qs[qsel] + row * 8;
        float* cr = Cs + tileL * XS_STRIDE + row * 8;
        *(float4*)(cr)     = make_float4(__fmul_rn(v0.x, Qt[0]), __fmul_rn(v0.y, Qt[1]),
                                         __fmul_rn(v0.z, Qt[2]), __fmul_rn(v0.w, Qt[3]));
        *(float4*)(cr + 4) = make_float4(__fmul_rn(v1.x, Qt[4]), __fmul_rn(v1.y, Qt[5]),
                                         __fmul_rn(v1.z, Qt[6]), __fmul_rn(v1.w, Qt[7]));
    }
    __syncthreads();

    float o[8];
    const float* cl = Cs + tileL * XS_STRIDE;
    switch (row) {
        case 0: inv_rows<0>(cl, o); break;
        case 1: inv_rows<1>(cl, o); break;
        case 2: inv_rows<2>(cl, o); break;
        case 3: inv_rows<3>(cl, o); break;
        case 4: inv_rows<4>(cl, o); break;
        case 5: inv_rows<5>(cl, o); break;
        case 6: inv_rows<6>(cl, o); break;
        case 7: inv_rows<7>(cl, o); break;
    }

    float* rp = rec + po + (size_t)row * width;
    *(float4*)(rp)     = make_float4(o[0], o[1], o[2], o[3]);
    *(float4*)(rp + 4) = make_float4(o[4], o[5], o[6], o[7]);
}

// ---- strip recon: one thread per 4 quads (8x2 pixels); bit-exact lerps ----
__global__ void __launch_bounds__(256) k_recon(float* __restrict__ out)
{
    int t = blockIdx.x * blockDim.x + threadIdx.x;
    if (t >= PLANE_C / 4) return;
    int sx = t & 63;
    int cy = (t >> 6) & 255;
    int b  = t >> 14;
    int cx0 = sx << 2;

    size_t cb = (size_t)b * CH2 * CW2;
    const float* Up = g_rU + cb;
    const float* Vp = g_rV + cb;

    int cym = max(cy - 1, 0), cyp = min(cy + 1, 255);
    bool y_top = (cy == 0), y_bot = (cy == 255);
    int colL = max(cx0 - 1, 0);
    int colR = min(cx0 + 4, 255);

    float uA[6], uM[6], uP[6], vA[6], vM[6], vP[6];
#define LOADROW(dst, base) { \
        float4 m = *(const float4*)((base) + cx0); \
        dst[1] = m.x; dst[2] = m.y; dst[3] = m.z; dst[4] = m.w; \
        dst[0] = (base)[colL]; dst[5] = (base)[colR]; }
    LOADROW(uA, Up + cym * CW2)
    LOADROW(uM, Up + cy  * CW2)
    LOADROW(uP, Up + cyp * CW2)
    LOADROW(vA, Vp + cym * CW2)
    LOADROW(vM, Vp + cy  * CW2)
    LOADROW(vP, Vp + cyp * CW2)
#undef LOADROW

    float ue[6], uo[6], ve[6], vo[6];
#pragma unroll
    for (int c = 0; c < 6; c++) {
        ue[c] = y_top ? uM[c] : __fadd_rn(__fmul_rn(uA[c], 0.25f), __fmul_rn(uM[c], 0.75f));
        uo[c] = y_bot ? uM[c] : __fadd_rn(__fmul_rn(uM[c], 0.75f), __fmul_rn(uP[c], 0.25f));
        ve[c] = y_top ? vM[c] : __fadd_rn(__fmul_rn(vA[c], 0.25f), __fmul_rn(vM[c], 0.75f));
        vo[c] = y_bot ? vM[c] : __fadd_rn(__fmul_rn(vM[c], 0.75f), __fmul_rn(vP[c], 0.25f));
    }

    float u00[4], u01[4], u10[4], u11[4];
    float v00[4], v01[4], v10[4], v11[4];
#pragma unroll
    for (int j = 0; j < 4; j++) {
        int ci = j + 1;
        bool xl = (cx0 + j == 0);
        bool xr = (cx0 + j == 255);
        u00[j] = xl ? ue[ci] : __fadd_rn(__fmul_rn(ue[ci-1], 0.25f), __fmul_rn(ue[ci], 0.75f));
        u01[j] = xr ? ue[ci] : __fadd_rn(__fmul_rn(ue[ci], 0.75f), __fmul_rn(ue[ci+1], 0.25f));
        u10[j] = xl ? uo[ci] : __fadd_rn(__fmul_rn(uo[ci-1], 0.25f), __fmul_rn(uo[ci], 0.75f));
        u11[j] = xr ? uo[ci] : __fadd_rn(__fmul_rn(uo[ci], 0.75f), __fmul_rn(uo[ci+1], 0.25f));
        v00[j] = xl ? ve[ci] : __fadd_rn(__fmul_rn(ve[ci-1], 0.25f), __fmul_rn(ve[ci], 0.75f));
        v01[j] = xr ? ve[ci] : __fadd_rn(__fmul_rn(ve[ci], 0.75f), __fmul_rn(ve[ci+1], 0.25f));
        v10[j] = xl ? vo[ci] : __fadd_rn(__fmul_rn(vo[ci-1], 0.25f), __fmul_rn(vo[ci], 0.75f));
        v11[j] = xr ? vo[ci] : __fadd_rn(__fmul_rn(vo[ci], 0.75f), __fmul_rn(vo[ci+1], 0.25f));
    }

    size_t yo0 = ((size_t)b * IH + cy * 2) * IW + cx0 * 2;
    float4 ya0 = *(const float4*)(g_rY + yo0);
    float4 ya1 = *(const float4*)(g_rY + yo0 + 4);
    float4 yb0 = *(const float4*)(g_rY + yo0 + IW);
    float4 yb1 = *(const float4*)(g_rY + yo0 + IW + 4);
    float ytop[8] = {ya0.x, ya0.y, ya0.z, ya0.w, ya1.x, ya1.y, ya1.z, ya1.w};
    float ybot[8] = {yb0.x, yb0.y, yb0.z, yb0.w, yb1.x, yb1.y, yb1.z, yb1.w};

    float R0[8], G0[8], B0[8], R1[8], G1[8], B1[8];
#pragma unroll
    for (int k = 0; k < 8; k++) {
        int j = k >> 1;
        bool odd = k & 1;
        {
            float uu = __fadd_rn(odd ? u01[j] : u00[j], -128.0f);
            float vv = __fadd_rn(odd ? v01[j] : v00[j], -128.0f);
            float yv = ytop[k];
            float r  = __fadd_rn(yv, __fmul_rn(vv, 1.402f));
            float g  = __fadd_rn(__fadd_rn(yv, __fmul_rn(uu, -0.344136f)), __fmul_rn(vv, -0.714136f));
            float bl = __fadd_rn(yv, __fmul_rn(uu, 1.772f));
            R0[k] = __fdiv_rn(fminf(fmaxf(r,  0.f), 255.f), 255.0f);
            G0[k] = __fdiv_rn(fminf(fmaxf(g,  0.f), 255.f), 255.0f);
            B0[k] = __fdiv_rn(fminf(fmaxf(bl, 0.f), 255.f), 255.0f);
        }
        {
            float uu = __fadd_rn(odd ? u11[j] : u10[j], -128.0f);
            float vv = __fadd_rn(odd ? v11[j] : v10[j], -128.0f);
            float yv = ybot[k];
            float r  = __fadd_rn(yv, __fmul_rn(vv, 1.402f));
            float g  = __fadd_rn(__fadd_rn(yv, __fmul_rn(uu, -0.344136f)), __fmul_rn(vv, -0.714136f));
            float bl = __fadd_rn(yv, __fmul_rn(uu, 1.772f));
            R1[k] = __fdiv_rn(fminf(fmaxf(r,  0.f), 255.f), 255.0f);
            G1[k] = __fdiv_rn(fminf(fmaxf(g,  0.f), 255.f), 255.0f);
            B1[k] = __fdiv_rn(fminf(fmaxf(bl, 0.f), 255.f), 255.0f);
        }
    }

    size_t ob0 = (size_t)b * 3 * IH * IW + ((size_t)cy * 2) * IW + cx0 * 2;
    size_t ob1 = ob0 + IW;
#define STORE8(base, arr) { \
        *(float4*)(base)     = make_float4(arr[0], arr[1], arr[2], arr[3]); \
        *(float4*)((base)+4) = make_float4(arr[4], arr[5], arr[6], arr[7]); }
    STORE8(out + ob0, R0)
    STORE8(out + ob1, R1)
    STORE8(out + ob0 + IH * IW, G0)
    STORE8(out + ob1 + IH * IW, G1)
    STORE8(out + ob0 + 2 * IH * IW, B0)
    STORE8(out + ob1 + 2 * IH * IW, B1)
#undef STORE8
}

extern "C" void kernel_launch(void* const* d_in, const int* in_sizes, int n_in,
                              void* d_out, int out_size)
{
    const float* img = (const float*)d_in[0];
    const float* lq  = (const float*)d_in[1];
    const float* cq  = (const float*)d_in[2];
    float* out = (float*)d_out;

    // output layout: rgb | qY | qU | qV (reference return order, flattened)
    float* qY = out + 12582912;
    float* qU = out + 16777216;
    float* qV = out + 17825792;

    k_fwd<<<FWD_LUMA_BLKS + FWD_CHROMA_BLKS, 256>>>(img, lq, cq, qY, qU, qV);
    k_inv<<<NT_ALL / 32, 256>>>(lq, cq, qY, qU, qV);
    k_recon<<<(PLANE_C / 4 + 255) / 256, 256>>>(out);
}

// round 15
// speedup vs baseline: 2.4319x; 1.0730x over previous
#include <cuda_runtime.h>
#include <math.h>

#define NBATCH 16
#define IH 512
#define IW 512
#define CH2 256
#define CW2 256
#define PLANE_Y (NBATCH * IH * IW)
#define PLANE_C (NBATCH * CH2 * CW2)

#define NT_Y (NBATCH * 64 * 64)   // 65536 luma tiles
#define NT_C (NBATCH * 32 * 32)   // 16384 chroma tiles per plane
#define NT_ALL (NT_Y + 2 * NT_C)  // 98304

// ---- scratch planes (static device globals; no runtime allocation) ----
__device__ float g_Y[PLANE_Y];
__device__ float g_U[PLANE_C];
__device__ float g_V[PLANE_C];
__device__ float g_rY[PLANE_Y];
__device__ float g_rU[PLANE_C];
__device__ float g_rV[PLANE_C];

// ---- compile-time DCT tables, replicating numpy fp64->fp32 exactly ----
__host__ __device__ constexpr double kCosV(int k) {
    return (k == 0) ? 1.0
         : (k == 1) ? 0.98078528040323044913
         : (k == 2) ? 0.92387953251128675613
         : (k == 3) ? 0.83146961230254523708
         : (k == 4) ? 0.70710678118654752440
         : (k == 5) ? 0.55557023301960222474
         : (k == 6) ? 0.38268343236508977173
         : (k == 7) ? 0.19509032201612826785
         : 0.0;
}
__host__ __device__ constexpr double cos16(int k) {
    k &= 31;
    if (k > 16) k = 32 - k;
    return (k <= 8) ? kCosV(k) : -kCosV(16 - k);
}
__host__ __device__ constexpr float Dc(int i, int j) {
    return (float)((j == 0) ? 0.35355339059327376220
                            : 0.5 * cos16((2 * i + 1) * j));
}
struct WTab { float w[64][64]; };
__host__ __device__ constexpr WTab makeW() {
    WTab t{};
    for (int p = 0; p < 64; p++)
        for (int f = 0; f < 64; f++)
            t.w[p][f] = Dc(p >> 3, f >> 3) * Dc(p & 7, f & 7);  // fp32 product (jnp.kron)
    return t;
}
__device__ constexpr WTab WT = makeW();

// ---- tile geometry helper (unified Y/U/V tile index) ----
struct TileInfo {
    const float* plane;
    float*       rec;
    float*       qbase;
    int          width;
    int          qsel;
    size_t       po;
    int          tp;
};

__device__ __forceinline__ TileInfo tile_info(int tile, float* qY, float* qU, float* qV)
{
    TileInfo ti;
    int tp, nbx, height;
    if (tile < NT_Y) {
        tp = tile;           ti.plane = g_Y; ti.rec = g_rY; ti.qbase = qY;
        ti.width = IW;  height = IH;  ti.qsel = 0;
    } else if (tile < NT_Y + NT_C) {
        tp = tile - NT_Y;    ti.plane = g_U; ti.rec = g_rU; ti.qbase = qU;
        ti.width = CW2; height = CH2; ti.qsel = 1;
    } else {
        tp = tile - NT_Y - NT_C; ti.plane = g_V; ti.rec = g_rV; ti.qbase = qV;
        ti.width = CW2; height = CH2; ti.qsel = 1;
    }
    nbx = ti.width >> 3;
    int nbpi = (height >> 3) * nbx;
    int b  = tp / nbpi, r = tp - b * nbpi;
    int by = r / nbx,  bx = r - by * nbx;
    ti.po = ((size_t)b * height + by * 8) * ti.width + bx * 8;
    ti.tp = tp;
    return ti;
}

// ---- RGB -> YUV (+128 chroma) and 2x2 chroma mean (validated bit-exact) ----
__global__ void k_csc(const float* __restrict__ img)
{
    int t = blockIdx.x * blockDim.x + threadIdx.x;
    if (t >= PLANE_C) return;
    int cx = t & 255;
    int cy = (t >> 8) & 255;
    int b  = t >> 16;
    const float* Rp = img + (size_t)b * 3 * IH * IW;
    const float* Gp = Rp + IH * IW;
    const float* Bp = Rp + 2 * IH * IW;
    int o0 = (cy * 2) * IW + cx * 2;
    int o1 = o0 + IW;
    float2 r0 = *(const float2*)(Rp + o0), r1 = *(const float2*)(Rp + o1);
    float2 g0 = *(const float2*)(Gp + o0), g1 = *(const float2*)(Gp + o1);
    float2 b0 = *(const float2*)(Bp + o0), b1 = *(const float2*)(Bp + o1);

    float rr[4] = {r0.x, r0.y, r1.x, r1.y};
    float gg[4] = {g0.x, g0.y, g1.x, g1.y};
    float bb[4] = {b0.x, b0.y, b1.x, b1.y};
    float y[4], u[4], v[4];
#pragma unroll
    for (int i = 0; i < 4; i++) {
        float r  = __fmul_rn(rr[i], 255.0f);
        float g  = __fmul_rn(gg[i], 255.0f);
        float bl = __fmul_rn(bb[i], 255.0f);
        y[i] = __fadd_rn(__fadd_rn(__fmul_rn(r, 0.299f),
                                   __fmul_rn(g, 0.587f)),
                         __fmul_rn(bl, 0.114f));
        u[i] = __fadd_rn(__fadd_rn(__fadd_rn(__fmul_rn(r, -0.168736f),
                                             __fmul_rn(g, -0.331264f)),
                                   __fmul_rn(bl, 0.5f)), 128.0f);
        v[i] = __fadd_rn(__fadd_rn(__fadd_rn(__fmul_rn(r, 0.5f),
                                             __fmul_rn(g, -0.418688f)),
                                   __fmul_rn(bl, -0.081312f)), 128.0f);
    }
    float* yb = g_Y + (size_t)b * IH * IW;
    *(float2*)(yb + o0) = make_float2(y[0], y[1]);
    *(float2*)(yb + o1) = make_float2(y[2], y[3]);
    g_U[t] = __fmul_rn(__fadd_rn(__fadd_rn(u[0], u[1]), __fadd_rn(u[2], u[3])), 0.25f);
    g_V[t] = __fmul_rn(__fadd_rn(__fadd_rn(v[0], v[1]), __fadd_rn(v[2], v[3])), 0.25f);
}

// ---- forward accumulation for f-group FG ----
template<int FG>
__device__ __forceinline__ void fwd_accum(const float* __restrict__ xs, float a[8])
{
#pragma unroll
    for (int pp = 0; pp < 64; pp++) {
        float xv = xs[pp];
#pragma unroll
        for (int u = 0; u < 8; u++)
            a[u] = fmaf(xv, WT.w[pp][FG * 8 + u], a[u]);
    }
}

// ---- fused forward: all planes, 8 threads/tile via warp-specialized f-groups ----
// (byte-identical to the round-9 kernel that passed at 86.5us)
__global__ void __launch_bounds__(256) k_fwd(const float* __restrict__ lq,
                                             const float* __restrict__ cq,
                                             float* __restrict__ qY,
                                             float* __restrict__ qU,
                                             float* __restrict__ qV)
{
    __shared__ float xs[32 * 65];
    __shared__ float Qs[2][64];

    int t = threadIdx.x;
    if (t < 64)              Qs[0][t]      = lq[t];
    else if (t < 128)        Qs[1][t - 64] = cq[t - 64];

    {
        int tileL = t & 31;
        int row   = t >> 5;
        int tile  = blockIdx.x * 32 + tileL;
        TileInfo ti = tile_info(tile, qY, qU, qV);
        const float* p = ti.plane + ti.po + (size_t)row * ti.width;
        float4 v0 = *(const float4*)(p);
        float4 v1 = *(const float4*)(p + 4);
        float* xr = xs + tileL * 65 + row * 8;
        xr[0] = v0.x - 128.f; xr[1] = v0.y - 128.f; xr[2] = v0.z - 128.f; xr[3] = v0.w - 128.f;
        xr[4] = v1.x - 128.f; xr[5] = v1.y - 128.f; xr[6] = v1.z - 128.f; xr[7] = v1.w - 128.f;
    }
    __syncthreads();

    int wid  = t >> 5;
    int lane = t & 31;
    int tile = blockIdx.x * 32 + lane;
    TileInfo ti = tile_info(tile, qY, qU, qV);

    float a[8] = {0.f, 0.f, 0.f, 0.f, 0.f, 0.f, 0.f, 0.f};
    const float* xl = xs + lane * 65;
    switch (wid) {
        case 0: fwd_accum<0>(xl, a); break;
        case 1: fwd_accum<1>(xl, a); break;
        case 2: fwd_accum<2>(xl, a); break;
        case 3: fwd_accum<3>(xl, a); break;
        case 4: fwd_accum<4>(xl, a); break;
        case 5: fwd_accum<5>(xl, a); break;
        case 6: fwd_accum<6>(xl, a); break;
        case 7: fwd_accum<7>(xl, a); break;
    }

    float q[8];
    const float* Qt = Qs[ti.qsel] + wid * 8;
#pragma unroll
    for (int u = 0; u < 8; u++)
        q[u] = rintf(__fdiv_rn(a[u], Qt[u]));

    float* qo = ti.qbase + (size_t)ti.tp * 64 + wid * 8;
    *(float4*)(qo)     = make_float4(q[0], q[1], q[2], q[3]);
    *(float4*)(qo + 4) = make_float4(q[4], q[5], q[6], q[7]);
}

// ---- inverse rows for output row R (immediate D consts) ----
template<int R>
__device__ __forceinline__ void inv_rows(const float* __restrict__ Cs, float o[8])
{
    float T[8];
#pragma unroll
    for (int j2 = 0; j2 < 8; j2++) {
        float s = 0.f;
#pragma unroll
        for (int j1 = 0; j1 < 8; j1++)
            s = fmaf(Dc(R, j1), Cs[j1 * 8 + j2], s);
        T[j2] = s;
    }
#pragma unroll
    for (int c = 0; c < 8; c++) {
        float s = 0.f;
#pragma unroll
        for (int j2 = 0; j2 < 8; j2++)
            s = fmaf(T[j2], Dc(c, j2), s);
        o[c] = s + 128.f;
    }
}

// ---- fused inverse: all planes, 8 threads/tile (round-9 version) ----
__global__ void __launch_bounds__(256) k_inv(const float* __restrict__ lq,
                                             const float* __restrict__ cq,
                                             const float* __restrict__ qY,
                                             const float* __restrict__ qU,
                                             const float* __restrict__ qV)
{
    __shared__ float Cs[32 * 65];
    __shared__ float Qs[2][64];

    int t = threadIdx.x;
    if (t < 64)       Qs[0][t]      = lq[t];
    else if (t < 128) Qs[1][t - 64] = cq[t - 64];
    __syncthreads();

    int tileL = t & 31;
    int row   = t >> 5;
    int tile  = blockIdx.x * 32 + tileL;
    TileInfo ti = tile_info(tile, (float*)qY, (float*)qU, (float*)qV);

    {
        const float* qi = ti.qbase + (size_t)ti.tp * 64 + row * 8;
        float4 v0 = *(const float4*)(qi);
        float4 v1 = *(const float4*)(qi + 4);
        const float* Qt = Qs[ti.qsel] + row * 8;
        float* cr = Cs + tileL * 65 + row * 8;
        cr[0] = __fmul_rn(v0.x, Qt[0]); cr[1] = __fmul_rn(v0.y, Qt[1]);
        cr[2] = __fmul_rn(v0.z, Qt[2]); cr[3] = __fmul_rn(v0.w, Qt[3]);
        cr[4] = __fmul_rn(v1.x, Qt[4]); cr[5] = __fmul_rn(v1.y, Qt[5]);
        cr[6] = __fmul_rn(v1.z, Qt[6]); cr[7] = __fmul_rn(v1.w, Qt[7]);
    }
    __syncthreads();

    float o[8];
    const float* cl = Cs + tileL * 65;
    switch (row) {
        case 0: inv_rows<0>(cl, o); break;
        case 1: inv_rows<1>(cl, o); break;
        case 2: inv_rows<2>(cl, o); break;
        case 3: inv_rows<3>(cl, o); break;
        case 4: inv_rows<4>(cl, o); break;
        case 5: inv_rows<5>(cl, o); break;
        case 6: inv_rows<6>(cl, o); break;
        case 7: inv_rows<7>(cl, o); break;
    }

    float* rp = ti.rec + ti.po + (size_t)row * ti.width;
    *(float4*)(rp)     = make_float4(o[0], o[1], o[2], o[3]);
    *(float4*)(rp + 4) = make_float4(o[4], o[5], o[6], o[7]);
}

// ---- strip recon: one thread per 4 quads (8x2 pixels); bit-exact lerps ----
// (proven identical outputs across rounds 10-14)
__global__ void __launch_bounds__(256) k_recon(float* __restrict__ out)
{
    int t = blockIdx.x * blockDim.x + threadIdx.x;
    if (t >= PLANE_C / 4) return;
    int sx = t & 63;
    int cy = (t >> 6) & 255;
    int b  = t >> 14;
    int cx0 = sx << 2;

    size_t cb = (size_t)b * CH2 * CW2;
    const float* Up = g_rU + cb;
    const float* Vp = g_rV + cb;

    int cym = max(cy - 1, 0), cyp = min(cy + 1, 255);
    bool y_top = (cy == 0), y_bot = (cy == 255);
    int colL = max(cx0 - 1, 0);
    int colR = min(cx0 + 4, 255);

    float uA[6], uM[6], uP[6], vA[6], vM[6], vP[6];
#define LOADROW(dst, base) { \
        float4 m = *(const float4*)((base) + cx0); \
        dst[1] = m.x; dst[2] = m.y; dst[3] = m.z; dst[4] = m.w; \
        dst[0] = (base)[colL]; dst[5] = (base)[colR]; }
    LOADROW(uA, Up + cym * CW2)
    LOADROW(uM, Up + cy  * CW2)
    LOADROW(uP, Up + cyp * CW2)
    LOADROW(vA, Vp + cym * CW2)
    LOADROW(vM, Vp + cy  * CW2)
    LOADROW(vP, Vp + cyp * CW2)
#undef LOADROW

    float ue[6], uo[6], ve[6], vo[6];
#pragma unroll
    for (int c = 0; c < 6; c++) {
        ue[c] = y_top ? uM[c] : __fadd_rn(__fmul_rn(uA[c], 0.25f), __fmul_rn(uM[c], 0.75f));
        uo[c] = y_bot ? uM[c] : __fadd_rn(__fmul_rn(uM[c], 0.75f), __fmul_rn(uP[c], 0.25f));
        ve[c] = y_top ? vM[c] : __fadd_rn(__fmul_rn(vA[c], 0.25f), __fmul_rn(vM[c], 0.75f));
        vo[c] = y_bot ? vM[c] : __fadd_rn(__fmul_rn(vM[c], 0.75f), __fmul_rn(vP[c], 0.25f));
    }

    float u00[4], u01[4], u10[4], u11[4];
    float v00[4], v01[4], v10[4], v11[4];
#pragma unroll
    for (int j = 0; j < 4; j++) {
        int ci = j + 1;
        bool xl = (cx0 + j == 0);
        bool xr = (cx0 + j == 255);
        u00[j] = xl ? ue[ci] : __fadd_rn(__fmul_rn(ue[ci-1], 0.25f), __fmul_rn(ue[ci], 0.75f));
        u01[j] = xr ? ue[ci] : __fadd_rn(__fmul_rn(ue[ci], 0.75f), __fmul_rn(ue[ci+1], 0.25f));
        u10[j] = xl ? uo[ci] : __fadd_rn(__fmul_rn(uo[ci-1], 0.25f), __fmul_rn(uo[ci], 0.75f));
        u11[j] = xr ? uo[ci] : __fadd_rn(__fmul_rn(uo[ci], 0.75f), __fmul_rn(uo[ci+1], 0.25f));
        v00[j] = xl ? ve[ci] : __fadd_rn(__fmul_rn(ve[ci-1], 0.25f), __fmul_rn(ve[ci], 0.75f));
        v01[j] = xr ? ve[ci] : __fadd_rn(__fmul_rn(ve[ci], 0.75f), __fmul_rn(ve[ci+1], 0.25f));
        v10[j] = xl ? vo[ci] : __fadd_rn(__fmul_rn(vo[ci-1], 0.25f), __fmul_rn(vo[ci], 0.75f));
        v11[j] = xr ? vo[ci] : __fadd_rn(__fmul_rn(vo[ci], 0.75f), __fmul_rn(vo[ci+1], 0.25f));
    }

    size_t yo0 = ((size_t)b * IH + cy * 2) * IW + cx0 * 2;
    float4 ya0 = *(const float4*)(g_rY + yo0);
    float4 ya1 = *(const float4*)(g_rY + yo0 + 4);
    float4 yb0 = *(const float4*)(g_rY + yo0 + IW);
    float4 yb1 = *(const float4*)(g_rY + yo0 + IW + 4);
    float ytop[8] = {ya0.x, ya0.y, ya0.z, ya0.w, ya1.x, ya1.y, ya1.z, ya1.w};
    float ybot[8] = {yb0.x, yb0.y, yb0.z, yb0.w, yb1.x, yb1.y, yb1.z, yb1.w};

    float R0[8], G0[8], B0[8], R1[8], G1[8], B1[8];
#pragma unroll
    for (int k = 0; k < 8; k++) {
        int j = k >> 1;
        bool odd = k & 1;
        {
            float uu = __fadd_rn(odd ? u01[j] : u00[j], -128.0f);
            float vv = __fadd_rn(odd ? v01[j] : v00[j], -128.0f);
            float yv = ytop[k];
            float r  = __fadd_rn(yv, __fmul_rn(vv, 1.402f));
            float g  = __fadd_rn(__fadd_rn(yv, __fmul_rn(uu, -0.344136f)), __fmul_rn(vv, -0.714136f));
            float bl = __fadd_rn(yv, __fmul_rn(uu, 1.772f));
            R0[k] = __fdiv_rn(fminf(fmaxf(r,  0.f), 255.f), 255.0f);
            G0[k] = __fdiv_rn(fminf(fmaxf(g,  0.f), 255.f), 255.0f);
            B0[k] = __fdiv_rn(fminf(fmaxf(bl, 0.f), 255.f), 255.0f);
        }
        {
            float uu = __fadd_rn(odd ? u11[j] : u10[j], -128.0f);
            float vv = __fadd_rn(odd ? v11[j] : v10[j], -128.0f);
            float yv = ybot[k];
            float r  = __fadd_rn(yv, __fmul_rn(vv, 1.402f));
            float g  = __fadd_rn(__fadd_rn(yv, __fmul_rn(uu, -0.344136f)), __fmul_rn(vv, -0.714136f));
            float bl = __fadd_rn(yv, __fmul_rn(uu, 1.772f));
            R1[k] = __fdiv_rn(fminf(fmaxf(r,  0.f), 255.f), 255.0f);
            G1[k] = __fdiv_rn(fminf(fmaxf(g,  0.f), 255.f), 255.0f);
            B1[k] = __fdiv_rn(fminf(fmaxf(bl, 0.f), 255.f), 255.0f);
        }
    }

    size_t ob0 = (size_t)b * 3 * IH * IW + ((size_t)cy * 2) * IW + cx0 * 2;
    size_t ob1 = ob0 + IW;
#define STORE8(base, arr) { \
        *(float4*)(base)     = make_float4(arr[0], arr[1], arr[2], arr[3]); \
        *(float4*)((base)+4) = make_float4(arr[4], arr[5], arr[6], arr[7]); }
    STORE8(out + ob0, R0)
    STORE8(out + ob1, R1)
    STORE8(out + ob0 + IH * IW, G0)
    STORE8(out + ob1 + IH * IW, G1)
    STORE8(out + ob0 + 2 * IH * IW, B0)
    STORE8(out + ob1 + 2 * IH * IW, B1)
#undef STORE8
}

extern "C" void kernel_launch(void* const* d_in, const int* in_sizes, int n_in,
                              void* d_out, int out_size)
{
    const float* img = (const float*)d_in[0];
    const float* lq  = (const float*)d_in[1];
    const float* cq  = (const float*)d_in[2];
    float* out = (float*)d_out;

    // output layout: rgb | qY | qU | qV (reference return order, flattened)
    float* qY = out + 12582912;
    float* qU = out + 16777216;
    float* qV = out + 17825792;

    k_csc<<<(PLANE_C + 255) / 256, 256>>>(img);
    k_fwd<<<NT_ALL / 32, 256>>>(lq, cq, qY, qU, qV);
    k_inv<<<NT_ALL / 32, 256>>>(lq, cq, qY, qU, qV);
    k_recon<<<(PLANE_C / 4 + 255) / 256, 256>>>(out);
}

// round 16
// speedup vs baseline: 2.6411x; 1.0860x over previous
#include <cuda_runtime.h>
#include <math.h>

#define NBATCH 16
#define IH 512
#define IW 512
#define CH2 256
#define CW2 256
#define PLANE_Y (NBATCH * IH * IW)
#define PLANE_C (NBATCH * CH2 * CW2)

#define NT_Y (NBATCH * 64 * 64)   // 65536 luma tiles
#define NT_C (NBATCH * 32 * 32)   // 16384 chroma tiles per plane
#define NT_ALL (NT_Y + 2 * NT_C)  // 98304

// ---- scratch planes (static device globals; no runtime allocation) ----
__device__ float g_Y[PLANE_Y];
__device__ float g_U[PLANE_C];
__device__ float g_V[PLANE_C];
__device__ float g_rY[PLANE_Y];
__device__ float g_rU[PLANE_C];
__device__ float g_rV[PLANE_C];

// ---- compile-time DCT tables, replicating numpy fp64->fp32 exactly ----
__host__ __device__ constexpr double kCosV(int k) {
    return (k == 0) ? 1.0
         : (k == 1) ? 0.98078528040323044913
         : (k == 2) ? 0.92387953251128675613
         : (k == 3) ? 0.83146961230254523708
         : (k == 4) ? 0.70710678118654752440
         : (k == 5) ? 0.55557023301960222474
         : (k == 6) ? 0.38268343236508977173
         : (k == 7) ? 0.19509032201612826785
         : 0.0;
}
__host__ __device__ constexpr double cos16(int k) {
    k &= 31;
    if (k > 16) k = 32 - k;
    return (k <= 8) ? kCosV(k) : -kCosV(16 - k);
}
__host__ __device__ constexpr float Dc(int i, int j) {
    return (float)((j == 0) ? 0.35355339059327376220
                            : 0.5 * cos16((2 * i + 1) * j));
}
struct WTab { float w[64][64]; };
__host__ __device__ constexpr WTab makeW() {
    WTab t{};
    for (int p = 0; p < 64; p++)
        for (int f = 0; f < 64; f++)
            t.w[p][f] = Dc(p >> 3, f >> 3) * Dc(p & 7, f & 7);  // fp32 product (jnp.kron)
    return t;
}
__device__ constexpr WTab WT = makeW();

// ---- tile geometry helper (unified Y/U/V tile index) ----
struct TileInfo {
    const float* plane;
    float*       rec;
    float*       qbase;
    int          width;
    int          qsel;
    size_t       po;
    int          tp;
};

__device__ __forceinline__ TileInfo tile_info(int tile, float* qY, float* qU, float* qV)
{
    TileInfo ti;
    int tp, nbx, height;
    if (tile < NT_Y) {
        tp = tile;           ti.plane = g_Y; ti.rec = g_rY; ti.qbase = qY;
        ti.width = IW;  height = IH;  ti.qsel = 0;
    } else if (tile < NT_Y + NT_C) {
        tp = tile - NT_Y;    ti.plane = g_U; ti.rec = g_rU; ti.qbase = qU;
        ti.width = CW2; height = CH2; ti.qsel = 1;
    } else {
        tp = tile - NT_Y - NT_C; ti.plane = g_V; ti.rec = g_rV; ti.qbase = qV;
        ti.width = CW2; height = CH2; ti.qsel = 1;
    }
    nbx = ti.width >> 3;
    int nbpi = (height >> 3) * nbx;
    int b  = tp / nbpi, r = tp - b * nbpi;
    int by = r / nbx,  bx = r - by * nbx;
    ti.po = ((size_t)b * height + by * 8) * ti.width + bx * 8;
    ti.tp = tp;
    return ti;
}

// ---- RGB -> YUV (+128 chroma) and 2x2 chroma mean (validated bit-exact) ----
__global__ void k_csc(const float* __restrict__ img)
{
    int t = blockIdx.x * blockDim.x + threadIdx.x;
    if (t >= PLANE_C) return;
    int cx = t & 255;
    int cy = (t >> 8) & 255;
    int b  = t >> 16;
    const float* Rp = img + (size_t)b * 3 * IH * IW;
    const float* Gp = Rp + IH * IW;
    const float* Bp = Rp + 2 * IH * IW;
    int o0 = (cy * 2) * IW + cx * 2;
    int o1 = o0 + IW;
    float2 r0 = *(const float2*)(Rp + o0), r1 = *(const float2*)(Rp + o1);
    float2 g0 = *(const float2*)(Gp + o0), g1 = *(const float2*)(Gp + o1);
    float2 b0 = *(const float2*)(Bp + o0), b1 = *(const float2*)(Bp + o1);

    float rr[4] = {r0.x, r0.y, r1.x, r1.y};
    float gg[4] = {g0.x, g0.y, g1.x, g1.y};
    float bb[4] = {b0.x, b0.y, b1.x, b1.y};
    float y[4], u[4], v[4];
#pragma unroll
    for (int i = 0; i < 4; i++) {
        float r  = __fmul_rn(rr[i], 255.0f);
        float g  = __fmul_rn(gg[i], 255.0f);
        float bl = __fmul_rn(bb[i], 255.0f);
        y[i] = __fadd_rn(__fadd_rn(__fmul_rn(r, 0.299f),
                                   __fmul_rn(g, 0.587f)),
                         __fmul_rn(bl, 0.114f));
        u[i] = __fadd_rn(__fadd_rn(__fadd_rn(__fmul_rn(r, -0.168736f),
                                             __fmul_rn(g, -0.331264f)),
                                   __fmul_rn(bl, 0.5f)), 128.0f);
        v[i] = __fadd_rn(__fadd_rn(__fadd_rn(__fmul_rn(r, 0.5f),
                                             __fmul_rn(g, -0.418688f)),
                                   __fmul_rn(bl, -0.081312f)), 128.0f);
    }
    float* yb = g_Y + (size_t)b * IH * IW;
    *(float2*)(yb + o0) = make_float2(y[0], y[1]);
    *(float2*)(yb + o1) = make_float2(y[2], y[3]);
    g_U[t] = __fmul_rn(__fadd_rn(__fadd_rn(u[0], u[1]), __fadd_rn(u[2], u[3])), 0.25f);
    g_V[t] = __fmul_rn(__fadd_rn(__fadd_rn(v[0], v[1]), __fadd_rn(v[2], v[3])), 0.25f);
}

// ---- forward accumulation for f-group FG (R9-validated) ----
template<int FG>
__device__ __forceinline__ void fwd_accum(const float* __restrict__ xs, float a[8])
{
#pragma unroll
    for (int pp = 0; pp < 64; pp++) {
        float xv = xs[pp];
#pragma unroll
        for (int u = 0; u < 8; u++)
            a[u] = fmaf(xv, WT.w[pp][FG * 8 + u], a[u]);
    }
}

// ---- inverse rows for output row R (immediate D consts; R9-validated) ----
template<int R>
__device__ __forceinline__ void inv_rows(const float* __restrict__ Cs, float o[8])
{
    float T[8];
#pragma unroll
    for (int j2 = 0; j2 < 8; j2++) {
        float s = 0.f;
#pragma unroll
        for (int j1 = 0; j1 < 8; j1++)
            s = fmaf(Dc(R, j1), Cs[j1 * 8 + j2], s);
        T[j2] = s;
    }
#pragma unroll
    for (int c = 0; c < 8; c++) {
        float s = 0.f;
#pragma unroll
        for (int j2 = 0; j2 < 8; j2++)
            s = fmaf(T[j2], Dc(c, j2), s);
        o[c] = s + 128.f;
    }
}

// ---- fused forward DCT + quantize + dequant + inverse DCT ----
// R9 k_fwd (warp-specialized f-groups) with k_inv's tail folded in:
// thread (wid,lane) holds coefficient row wid of tile lane -> stage C=q*qt
// back into smem, sync, and run inv_rows<wid> for the same tile. Saves the
// q re-read and a whole launch; all arithmetic orders identical to R9.
__global__ void __launch_bounds__(256) k_fwd_inv(const float* __restrict__ lq,
                                                 const float* __restrict__ cq,
                                                 float* __restrict__ qY,
                                                 float* __restrict__ qU,
                                                 float* __restrict__ qV)
{
    __shared__ float xs[32 * 65];   // x in phase 1, reused as C in phase 3
    __shared__ float Qs[2][64];

    int t = threadIdx.x;
    if (t < 64)              Qs[0][t]      = lq[t];
    else if (t < 128)        Qs[1][t - 64] = cq[t - 64];

    {
        int tileL = t & 31;
        int row   = t >> 5;
        int tile  = blockIdx.x * 32 + tileL;
        TileInfo ti = tile_info(tile, qY, qU, qV);
        const float* p = ti.plane + ti.po + (size_t)row * ti.width;
        float4 v0 = *(const float4*)(p);
        float4 v1 = *(const float4*)(p + 4);
        float* xr = xs + tileL * 65 + row * 8;
        xr[0] = v0.x - 128.f; xr[1] = v0.y - 128.f; xr[2] = v0.z - 128.f; xr[3] = v0.w - 128.f;
        xr[4] = v1.x - 128.f; xr[5] = v1.y - 128.f; xr[6] = v1.z - 128.f; xr[7] = v1.w - 128.f;
    }
    __syncthreads();

    int wid  = t >> 5;
    int lane = t & 31;
    int tile = blockIdx.x * 32 + lane;
    TileInfo ti = tile_info(tile, qY, qU, qV);

    float a[8] = {0.f, 0.f, 0.f, 0.f, 0.f, 0.f, 0.f, 0.f};
    const float* xl = xs + lane * 65;
    switch (wid) {
        case 0: fwd_accum<0>(xl, a); break;
        case 1: fwd_accum<1>(xl, a); break;
        case 2: fwd_accum<2>(xl, a); break;
        case 3: fwd_accum<3>(xl, a); break;
        case 4: fwd_accum<4>(xl, a); break;
        case 5: fwd_accum<5>(xl, a); break;
        case 6: fwd_accum<6>(xl, a); break;
        case 7: fwd_accum<7>(xl, a); break;
    }

    float q[8];
    const float* Qt = Qs[ti.qsel] + wid * 8;
#pragma unroll
    for (int u = 0; u < 8; u++)
        q[u] = rintf(__fdiv_rn(a[u], Qt[u]));

    float* qo = ti.qbase + (size_t)ti.tp * 64 + wid * 8;
    *(float4*)(qo)     = make_float4(q[0], q[1], q[2], q[3]);
    *(float4*)(qo + 4) = make_float4(q[4], q[5], q[6], q[7]);

    // ---- inverse tail (formerly k_inv) ----
    __syncthreads();   // all fwd reads of xs complete; safe to overwrite
    {
        float* cr = xs + lane * 65 + wid * 8;   // coefficient row wid of tile lane
        cr[0] = __fmul_rn(q[0], Qt[0]); cr[1] = __fmul_rn(q[1], Qt[1]);
        cr[2] = __fmul_rn(q[2], Qt[2]); cr[3] = __fmul_rn(q[3], Qt[3]);
        cr[4] = __fmul_rn(q[4], Qt[4]); cr[5] = __fmul_rn(q[5], Qt[5]);
        cr[6] = __fmul_rn(q[6], Qt[6]); cr[7] = __fmul_rn(q[7], Qt[7]);
    }
    __syncthreads();

    float o[8];
    const float* cl = xs + lane * 65;
    switch (wid) {
        case 0: inv_rows<0>(cl, o); break;
        case 1: inv_rows<1>(cl, o); break;
        case 2: inv_rows<2>(cl, o); break;
        case 3: inv_rows<3>(cl, o); break;
        case 4: inv_rows<4>(cl, o); break;
        case 5: inv_rows<5>(cl, o); break;
        case 6: inv_rows<6>(cl, o); break;
        case 7: inv_rows<7>(cl, o); break;
    }

    float* rp = ti.rec + ti.po + (size_t)wid * ti.width;
    *(float4*)(rp)     = make_float4(o[0], o[1], o[2], o[3]);
    *(float4*)(rp + 4) = make_float4(o[4], o[5], o[6], o[7]);
}

// ---- quad recon: one thread per 2x2 output quad (R9 version, 19.7us) ----
__global__ void __launch_bounds__(256) k_recon(float* __restrict__ out)
{
    int t = blockIdx.x * blockDim.x + threadIdx.x;
    if (t >= PLANE_C) return;
    int cx = t & 255;
    int cy = (t >> 8) & 255;
    int b  = t >> 16;

    size_t cb = (size_t)b * CH2 * CW2;
    const float* Up = g_rU + cb;
    const float* Vp = g_rV + cb;

    int cxm = max(cx - 1, 0), cxp = min(cx + 1, 255);
    int cym = max(cy - 1, 0), cyp = min(cy + 1, 255);
    bool y_top = (cy == 0), y_bot = (cy == 255);
    bool x_lft = (cx == 0), x_rgt = (cx == 255);

    int cols[3] = {cxm, cx, cxp};
    float ue[3], uo[3], ve[3], vo[3];
#pragma unroll
    for (int c = 0; c < 3; c++) {
        int col = cols[c];
        float ua = Up[cym * CW2 + col], um = Up[cy * CW2 + col], up = Up[cyp * CW2 + col];
        float va = Vp[cym * CW2 + col], vm = Vp[cy * CW2 + col], vp = Vp[cyp * CW2 + col];
        ue[c] = y_top ? um : __fadd_rn(__fmul_rn(ua, 0.25f), __fmul_rn(um, 0.75f));
        ve[c] = y_top ? vm : __fadd_rn(__fmul_rn(va, 0.25f), __fmul_rn(vm, 0.75f));
        uo[c] = y_bot ? um : __fadd_rn(__fmul_rn(um, 0.75f), __fmul_rn(up, 0.25f));
        vo[c] = y_bot ? vm : __fadd_rn(__fmul_rn(vm, 0.75f), __fmul_rn(vp, 0.25f));
    }

    float u00 = x_lft ? ue[1] : __fadd_rn(__fmul_rn(ue[0], 0.25f), __fmul_rn(ue[1], 0.75f));
    float u01 = x_rgt ? ue[1] : __fadd_rn(__fmul_rn(ue[1], 0.75f), __fmul_rn(ue[2], 0.25f));
    float u10 = x_lft ? uo[1] : __fadd_rn(__fmul_rn(uo[0], 0.25f), __fmul_rn(uo[1], 0.75f));
    float u11 = x_rgt ? uo[1] : __fadd_rn(__fmul_rn(uo[1], 0.75f), __fmul_rn(uo[2], 0.25f));
    float v00 = x_lft ? ve[1] : __fadd_rn(__fmul_rn(ve[0], 0.25f), __fmul_rn(ve[1], 0.75f));
    float v01 = x_rgt ? ve[1] : __fadd_rn(__fmul_rn(ve[1], 0.75f), __fmul_rn(ve[2], 0.25f));
    float v10 = x_lft ? vo[1] : __fadd_rn(__fmul_rn(vo[0], 0.25f), __fmul_rn(vo[1], 0.75f));
    float v11 = x_rgt ? vo[1] : __fadd_rn(__fmul_rn(vo[1], 0.75f), __fmul_rn(vo[2], 0.25f));

    size_t yo0 = ((size_t)b * IH + cy * 2) * IW + cx * 2;
    size_t yo1 = yo0 + IW;
    float2 yr0 = *(const float2*)(g_rY + yo0);
    float2 yr1 = *(const float2*)(g_rY + yo1);

    float yq[4] = {yr0.x, yr0.y, yr1.x, yr1.y};
    float uq[4] = {u00, u01, u10, u11};
    float vq[4] = {v00, v01, v10, v11};
    float R[4], G[4], B[4];
#pragma unroll
    for (int i = 0; i < 4; i++) {
        float uu = __fadd_rn(uq[i], -128.0f);
        float vv = __fadd_rn(vq[i], -128.0f);
        float yv = yq[i];
        float r  = __fadd_rn(yv, __fmul_rn(vv, 1.402f));
        float g  = __fadd_rn(__fadd_rn(yv, __fmul_rn(uu, -0.344136f)), __fmul_rn(vv, -0.714136f));
        float bl = __fadd_rn(yv, __fmul_rn(uu, 1.772f));
        R[i] = __fdiv_rn(fminf(fmaxf(r,  0.f), 255.f), 255.0f);
        G[i] = __fdiv_rn(fminf(fmaxf(g,  0.f), 255.f), 255.0f);
        B[i] = __fdiv_rn(fminf(fmaxf(bl, 0.f), 255.f), 255.0f);
    }

    size_t ob0 = (size_t)b * 3 * IH * IW + ((size_t)cy * 2) * IW + cx * 2;
    size_t ob1 = ob0 + IW;
    *(float2*)(out + ob0)                 = make_float2(R[0], R[1]);
    *(float2*)(out + ob1)                 = make_float2(R[2], R[3]);
    *(float2*)(out + ob0 + IH * IW)       = make_float2(G[0], G[1]);
    *(float2*)(out + ob1 + IH * IW)       = make_float2(G[2], G[3]);
    *(float2*)(out + ob0 + 2 * IH * IW)   = make_float2(B[0], B[1]);
    *(float2*)(out + ob1 + 2 * IH * IW)   = make_float2(B[2], B[3]);
}

extern "C" void kernel_launch(void* const* d_in, const int* in_sizes, int n_in,
                              void* d_out, int out_size)
{
    const float* img = (const float*)d_in[0];
    const float* lq  = (const float*)d_in[1];
    const float* cq  = (const float*)d_in[2];
    float* out = (float*)d_out;

    // output layout: rgb | qY | qU | qV (reference return order, flattened)
    float* qY = out + 12582912;
    float* qU = out + 16777216;
    float* qV = out + 17825792;

    k_csc<<<(PLANE_C + 255) / 256, 256>>>(img);
    k_fwd_inv<<<NT_ALL / 32, 256>>>(lq, cq, qY, qU, qV);
    k_recon<<<(PLANE_C + 255) / 256, 256>>>(out);
}